// round 17
// baseline (speedup 1.0000x reference)
#include <cuda_runtime.h>
#include <cstdint>

// Problem constants
#define A_BATCH 128
#define M_LEN   256
#define D_DIM   16
#define MM      255            // PDE grid size (M-1)
#define NTASK   384            // 3 PDE solves x 128 batch

// Ring: one slot per column of raw g values, R14 layout (12 words/lane:
// 8 data + 4 pad; quad stride 3 coprime to 32 -> conflict-free 16B access;
// SLOT_W % 32 == 0 -> slot-independent banks). RB=60 -> run-ahead 29 cols.
// Split pipelines: producer-top/consumer-A use regions 0..15 (rows 0..127),
// producer-bottom/consumer-B regions 16..31 (rows 128..255). Each half of a
// slot is independently versioned (disjoint bytes).
#define RB      60
#define SLOT_W  384            // 12 words * 32 lanes
#define SLOT_B  (SLOT_W * 4)   // 1536 bytes
#define RING_W  (RB * SLOT_W)  // 23040 words
#define DY_W    (MM * D_DIM)   // 4080 words
#define PUB_W   320            // pub[c] = K[128][c], padded for tail reads
#define PUB_OFF   (RING_W + DY_W)
#define FLAGS_OFF (PUB_OFF + PUB_W)
#define SMEM_FLOATS (FLAGS_OFF + 8)
#define SMEM_BYTES (SMEM_FLOATS * 4)   // 109,824 B -> 2 CTAs/SM co-resident

#define K12 0.0833333333333333f

typedef unsigned long long u64;
typedef unsigned int u32;

__device__ float g_partial[NTASK];
__device__ int   g_done = 0;       // last-CTA counter (reset by the last CTA)

__device__ __forceinline__ u64 pack2(float lo, float hi) {
    u64 r; asm("mov.b64 %0,{%1,%2};" : "=l"(r) : "f"(lo), "f"(hi)); return r;
}
__device__ __forceinline__ void unpack2(u64 v, float& lo, float& hi) {
    asm("mov.b64 {%0,%1},%2;" : "=f"(lo), "=f"(hi) : "l"(v));
}
__device__ __forceinline__ u64 fma2(u64 a, u64 b, u64 c) {
    u64 d; asm("fma.rn.f32x2 %0,%1,%2,%3;" : "=l"(d) : "l"(a), "l"(b), "l"(c)); return d;
}
__device__ __forceinline__ u64 mul2(u64 a, u64 b) {
    u64 d; asm("mul.rn.f32x2 %0,%1,%2;" : "=l"(d) : "l"(a), "l"(b)); return d;
}
__device__ __forceinline__ int lds_acq(u32 a) {
    int v; asm volatile("ld.acquire.cta.shared.b32 %0,[%1];" : "=r"(v) : "r"(a)); return v;
}
__device__ __forceinline__ void sts_rel(u32 a, int v) {
    asm volatile("st.release.cta.shared.b32 [%0],%1;" :: "r"(a), "r"(v));
}
__device__ __forceinline__ float lds_f(u32 a) {
    float v; asm volatile("ld.shared.f32 %0,[%1];" : "=f"(v) : "r"(a)); return v;
}
__device__ __forceinline__ void sts_f(u32 a, float v) {
    asm volatile("st.shared.f32 [%0],%1;" :: "r"(a), "f"(v));
}
__device__ __forceinline__ void lds128(u32 a, float& x, float& y, float& z, float& w) {
    asm volatile("ld.shared.v4.f32 {%0,%1,%2,%3},[%4];"
                 : "=f"(x), "=f"(y), "=f"(z), "=f"(w) : "r"(a));
}
__device__ __forceinline__ void sts128(u32 a, float x, float y, float z, float w) {
    asm volatile("st.shared.v4.f32 [%0],{%1,%2,%3,%4};"
                 :: "r"(a), "f"(x), "f"(y), "f"(z), "f"(w));
}

// One CTA = one task = 128 threads, TWO producer->consumer pipelines:
//   w0 = producer rows 0..127, w2 = consumer-A rows 0..127 (4 rows/lane)
//   w1 = producer rows 128..255, w3 = consumer-B rows 128..255
// A's lane 31 publishes row-127 K values to pub[]; B's lane 0 consumes them
// (gated on A's progress flag). This splits the old single consumer's
// ~56 fma/step across two SMSPs (~28 each) -> per-SMSP issue load halves.
__global__ void __launch_bounds__(128, 2) sig_pde_kernel(
    const float* __restrict__ X, const float* __restrict__ Y,
    float* __restrict__ out)
{
    extern __shared__ float smem[];
    u32 sb;
    asm("{.reg .u64 t; cvta.to.shared.u64 t,%1; cvt.u32.u64 %0,t;}"
        : "=r"(sb) : "l"(smem));

    const int t    = threadIdx.x;
    const int q    = t >> 5;           // warp 0..3
    const int lane = t & 31;

    const int task = (int)blockIdx.x;
    const int pde  = task >> 7;        // 0:(X,X) 1:(Y,Y) 2:(X,Y)
    const int a    = task & 127;
    const float* rowsrc = (pde == 1 ? Y : X) + (size_t)a * (M_LEN * D_DIM);
    const float* colsrc = (pde == 0 ? X : Y) + (size_t)a * (M_LEN * D_DIM);

    float* s_dY = smem + RING_W;
    const u32 ring_b  = sb;
    const u32 pub_b   = sb + PUB_OFF * 4;
    const u32 flags_b = sb + FLAGS_OFF * 4;
    // flags: [0]=doneA(prod top) [1]=doneB(prod bot) [2]=consA [3]=consB
    const u32 fdA = flags_b, fdB = flags_b + 4;
    const u32 fcA = flags_b + 8, fcB = flags_b + 12;

    // dY[j][k] = colsrc[j+1][k] - colsrc[j][k]
    for (int idx = t; idx < DY_W; idx += 128)
        s_dY[idx] = colsrc[idx + D_DIM] - colsrc[idx];
    if (t < 4) ((volatile int*)(smem + FLAGS_OFF))[t] = -1;
    if (t == 4) smem[PUB_OFF] = 1.0f;          // pub[0] = K[128][0] = 1
    __syncthreads();   // the ONLY cta barrier

    if (q < 2) {
        // =================== PRODUCER (w0 top / w1 bottom) ===================
        const int half = q;                     // 0: rows 0..127, 1: 128..255
        const int base = half * 128;
        const u32 done_a = half ? fdB : fdA;
        const u32 cons_a = half ? fcB : fcA;

        // dX for rows base+4*lane .. +3 in registers (f32x2 packed)
        u64 dxp[4][8];
#pragma unroll
        for (int r = 0; r < 4; r++) {
            const int i = base + 4 * lane + r;
            if (i < MM) {
                const float4* pa = reinterpret_cast<const float4*>(rowsrc + i * D_DIM);
                const float4* pb = reinterpret_cast<const float4*>(rowsrc + (i + 1) * D_DIM);
#pragma unroll
                for (int k = 0; k < 4; k++) {
                    float4 va = pa[k], vb = pb[k];
                    dxp[r][2 * k]     = pack2(vb.x - va.x, vb.y - va.y);
                    dxp[r][2 * k + 1] = pack2(vb.z - va.z, vb.w - va.w);
                }
            } else {                            // row 255 -> g = 0
#pragma unroll
                for (int k = 0; k < 8; k++) dxp[r][k] = 0ull;
            }
        }

        int cons_c = -1;
        // lane region: 48B*(lane>>1) + 16B*(lane&1), + 768B for bottom half
        u32 colb = ring_b + (u32)half * 768u + 48u * (u32)(lane >> 1)
                 + 16u * (u32)(lane & 1);
        const u32 colb_lim = colb + (u32)(RB * SLOT_B);
        const ulonglong2* dyp = reinterpret_cast<const ulonglong2*>(s_dY);

        auto produce = [&](ulonglong2 y0, ulonglong2 y1,
                           ulonglong2 y2, ulonglong2 y3) {
            float gv[4];
#pragma unroll
            for (int r = 0; r < 4; r++) {
                u64 acc = mul2(dxp[r][0], y0.x);
                acc = fma2(dxp[r][1], y0.y, acc);
                acc = fma2(dxp[r][2], y1.x, acc);
                acc = fma2(dxp[r][3], y1.y, acc);
                acc = fma2(dxp[r][4], y2.x, acc);
                acc = fma2(dxp[r][5], y2.y, acc);
                acc = fma2(dxp[r][6], y3.x, acc);
                acc = fma2(dxp[r][7], y3.y, acc);
                float lo, hi; unpack2(acc, lo, hi);
                gv[r] = lo + hi;
            }
            sts128(colb, gv[0], gv[1], gv[2], gv[3]);
            dyp  += 4;                          // next column (16 floats)
            colb += SLOT_B;
            if (colb >= colb_lim) colb -= (u32)(RB * SLOT_B);
        };

        int c = 0;
#pragma unroll 1
        for (; c < RB; c++) {                   // no ring wait needed
            produce(dyp[0], dyp[1], dyp[2], dyp[3]);
            if (lane == 0) sts_rel(done_a, c);
        }
#pragma unroll 1
        for (; c < MM; c++) {                   // slot reuse: wait cons>=c-29
            const ulonglong2 y0 = dyp[0], y1 = dyp[1], y2 = dyp[2], y3 = dyp[3];
            const int need = c - (RB - 31);
            while (cons_c < need) cons_c = lds_acq(cons_a);   // bare spin
            produce(y0, y1, y2, y3);
            if (lane == 0) sts_rel(done_a, c);
        }
    } else if (q == 2) {
        // =================== CONSUMER A (rows 0..127) ===================
        float L[4];
#pragma unroll
        for (int r = 0; r < 4; r++) L[r] = 1.0f;     // K[4l+r+1][0] = 1
        float nb_prev = 1.0f, last = 0.0f;
        u32 ad = ring_b + 48u * (u32)(lane >> 1) + 16u * (u32)(lane & 1);
        const u32 ad_lim = ad + (u32)(RB * SLOT_B);
        int fp = -1;

        auto waitf = [&](int& f, u32 fa, int s) {
            if (f < s) { do { f = lds_acq(fa); } while (f < s); }
        };
        auto loadR = [&](float* G) {
            lds128(ad, G[0], G[1], G[2], G[3]);
            ad += SLOT_B;
            if (ad >= ad_lim) ad -= (u32)(RB * SLOT_B);
        };
        auto chain = [&](const float* G, float nb_new) {
            float c1[4], c2[4];
#pragma unroll
            for (int r = 0; r < 4; r++) {
                const float g = G[r];
                const float h = g * g;
                const float u = fmaf(h,  K12, 1.0f);
                c1[r] = fmaf(g, 0.5f, u);
                c2[r] = fmaf(h, -K12, 1.0f);
            }
            const float up0 = (lane == 0) ? 1.0f : nb_new;
            const float dg0 = (lane == 0) ? 1.0f : nb_prev;
            float P0 = fmaf(L[0], c1[0], -(dg0  * c2[0]));
            float P1 = fmaf(L[1], c1[1], -(L[0] * c2[1]));
            float P2 = fmaf(L[2], c1[2], -(L[1] * c2[2]));
            float P3 = fmaf(L[3], c1[3], -(L[2] * c2[3]));
            float k = fmaf(up0, c1[0], P0); L[0] = k;
            k = fmaf(k, c1[1], P1); L[1] = k;
            k = fmaf(k, c1[2], P2); L[2] = k;
            k = fmaf(k, c1[3], P3); L[3] = k;
            last = k;
            nb_prev = nb_new;
        };
        auto body_ld = [&](float nb_new) {
            float G[4]; loadR(G); chain(G, nb_new);
        };
        // lane 31 publishes row-127 boundary: pub[s-30] = K[128][s-30]
        auto pubst = [&](int s) {
            if (lane == 31) sts_f(pub_b + 4u * (u32)(s - 30), last);
        };

        // ---- ramp: s = 0..32 ----
#pragma unroll 1
        for (int s = 0; s < 33; s++) {
            float nb = __shfl_up_sync(0xffffffffu, last, 1);
            waitf(fp, fdA, s);
            if (lane <= s) body_ld(nb);
            if (s >= 31) pubst(s);
            if (lane == 0) sts_rel(fcA, s);
        }
        // ---- steady: steps 33..252 (pipelined, 2-step groups) ----
        float R[4], T[4];
        waitf(fp, fdA, 33);
        loadR(R);                                    // col 33
#pragma unroll 1
        for (int s = 33; s < 252; s += 2) {
            { float nb = __shfl_up_sync(0xffffffffu, last, 1);
              waitf(fp, fdA, s + 1); loadR(T); chain(R, nb); pubst(s); }
            { float nb = __shfl_up_sync(0xffffffffu, last, 1);
              waitf(fp, fdA, s + 2); loadR(R); chain(T, nb); pubst(s + 1); }
            if (lane == 0) sts_rel(fcA, s + 1);
        }
        // steps 33..252 done; R holds col 253.
        { float nb = __shfl_up_sync(0xffffffffu, last, 1);
          waitf(fp, fdA, 254); loadR(T); chain(R, nb); pubst(253); }   // 253
        { float nb = __shfl_up_sync(0xffffffffu, last, 1);
          chain(T, nb); pubst(254); }                                  // 254
        if (lane == 0) sts_rel(fcA, 254);
        // ---- tail: s = 255..285 ----
#pragma unroll 1
        for (int s = 255; s < 286; s++) {
            float nb = __shfl_up_sync(0xffffffffu, last, 1);
            if (lane >= s - 254) body_ld(nb);
            pubst(s);
        }
        if (lane == 0) sts_rel(fcA, 1 << 20);        // A fully done
    } else {
        // =================== CONSUMER B (rows 128..255) ===================
        float L[4];
#pragma unroll
        for (int r = 0; r < 4; r++) L[r] = 1.0f;
        float nb_prev = 1.0f, last = 0.0f;
        float pu_prev = 1.0f;                        // pub[0] = 1
        u32 ad = ring_b + 768u + 48u * (u32)(lane >> 1) + 16u * (u32)(lane & 1);
        const u32 ad_lim = ad + (u32)(RB * SLOT_B);
        int fp = -1, fa = -1;

        auto waitf = [&](int& f, u32 faddr, int s) {
            if (f < s) { do { f = lds_acq(faddr); } while (f < s); }
        };
        auto loadR = [&](float* G) {
            lds128(ad, G[0], G[1], G[2], G[3]);
            ad += SLOT_B;
            if (ad >= ad_lim) ad -= (u32)(RB * SLOT_B);
        };
        auto chain = [&](const float* G, float nb_new, int tt) {
            // boundary from pub (uniform address -> broadcast load)
            const float pu = lds_f(pub_b + 4u * (u32)(tt + 1)); // pub[t+1]
            float c1[4], c2[4];
#pragma unroll
            for (int r = 0; r < 4; r++) {
                const float g = G[r];
                const float h = g * g;
                const float u = fmaf(h,  K12, 1.0f);
                c1[r] = fmaf(g, 0.5f, u);
                c2[r] = fmaf(h, -K12, 1.0f);
            }
            const float up0 = (lane == 0) ? pu      : nb_new;
            const float dg0 = (lane == 0) ? pu_prev : nb_prev;
            float P0 = fmaf(L[0], c1[0], -(dg0  * c2[0]));
            float P1 = fmaf(L[1], c1[1], -(L[0] * c2[1]));
            float P2 = fmaf(L[2], c1[2], -(L[1] * c2[2]));
            float P3 = fmaf(L[3], c1[3], -(L[2] * c2[3]));
            float k = fmaf(up0, c1[0], P0); L[0] = k;
            k = fmaf(k, c1[1], P1); L[1] = k;
            k = fmaf(k, c1[2], P2); L[2] = k;
            k = fmaf(k, c1[3], P3); L[3] = k;
            last = k;
            nb_prev = nb_new;
            pu_prev = pu;
        };
        auto body_ld = [&](float nb_new, int tt) {
            float G[4]; loadR(G); chain(G, nb_new, tt);
        };

        // ---- ramp: t = 0..32 ----
#pragma unroll 1
        for (int tt = 0; tt < 33; tt++) {
            float nb = __shfl_up_sync(0xffffffffu, last, 1);
            waitf(fp, fdB, tt);
            waitf(fa, fcA, tt + 31);                 // pub[t+1] ready
            if (lane <= tt) body_ld(nb, tt);
            if (lane == 0) sts_rel(fcB, tt);
        }
        // ---- steady: steps 33..252 ----
        float R[4], T[4];
        waitf(fp, fdB, 33);
        loadR(R);
#pragma unroll 1
        for (int tt = 33; tt < 252; tt += 2) {
            { float nb = __shfl_up_sync(0xffffffffu, last, 1);
              waitf(fp, fdB, tt + 1); loadR(T);
              waitf(fa, fcA, tt + 31); chain(R, nb, tt); }
            { float nb = __shfl_up_sync(0xffffffffu, last, 1);
              waitf(fp, fdB, tt + 2); loadR(R);
              waitf(fa, fcA, tt + 32); chain(T, nb, tt + 1); }
            if (lane == 0) sts_rel(fcB, tt + 1);
        }
        { float nb = __shfl_up_sync(0xffffffffu, last, 1);
          waitf(fp, fdB, 254); loadR(T);
          waitf(fa, fcA, 284); chain(R, nb, 253); }                    // 253
        { float nb = __shfl_up_sync(0xffffffffu, last, 1);
          waitf(fa, fcA, 285); chain(T, nb, 254); }                    // 254
        if (lane == 0) sts_rel(fcB, 254);
        // ---- tail: t = 255..285 (lane 0 inactive; pub reads are pad) ----
#pragma unroll 1
        for (int tt = 255; tt < 286; tt++) {
            float nb = __shfl_up_sync(0xffffffffu, last, 1);
            if (lane >= tt - 254) body_ld(nb, tt);
        }
        if (lane == 0) sts_rel(fcB, 1 << 20);
        // K[255][255] = L[2] of lane 31 (row 254 = base 252 + r=2)
        if (lane == 31) g_partial[task] = L[2];

        // ---- fused reduction: last CTA sums all partials ----
        int old = 0;
        if (lane == 31) {
            __threadfence();
            old = atomicAdd(&g_done, 1);
        }
        old = __shfl_sync(0xffffffffu, old, 31);
        if (old == NTASK - 1) {
            __threadfence();
            float v = 0.0f;
#pragma unroll
            for (int i = lane; i < NTASK; i += 32) {
                const float w = (i >= 256) ? -2.0f : 1.0f;
                v += w * g_partial[i];
            }
#pragma unroll
            for (int off = 16; off > 0; off >>= 1)
                v += __shfl_down_sync(0xffffffffu, v, off);
            if (lane == 0) {
                g_done = 0;                          // reset for next replay
                out[0] = v * (1.0f / (float)A_BATCH);
            }
        }
    }
}

extern "C" void kernel_launch(void* const* d_in, const int* in_sizes, int n_in,
                              void* d_out, int out_size)
{
    const float* X = (const float*)d_in[0];
    const float* Y = (const float*)d_in[1];
    float* out = (float*)d_out;

    cudaFuncSetAttribute(sig_pde_kernel,
                         cudaFuncAttributeMaxDynamicSharedMemorySize, SMEM_BYTES);

    sig_pde_kernel<<<NTASK, 128, SMEM_BYTES>>>(X, Y, out);
}